// round 4
// baseline (speedup 1.0000x reference)
#include <cuda_runtime.h>

#define HW   (128*128)        // 16384 pixels per (b,c) plane
#define CHW  (64*HW)          // one batch image, 64 channels
#define NPIX (4*HW)           // total pixels across batch

// Scratch tensors (allocation-free rule: __device__ globals)
__device__ float g_Q[4*CHW];
__device__ float g_V[4*CHW];
__device__ float g_O[4*CHW];

// ---------------------------------------------------------------------------
// conv1x1 body: out[b,f,p] = sum_c w[f,c]*in[b,c,p] + bias[f] (+ resid)
// Tile: 64 features x 128 pixels, 256 threads, 8f x 4px per thread.
// All shared traffic is LDS.128: weights transposed to [c][f] in smem
// (2 broadcast float4 per k), activations as lane-strided float4 (1 per k).
// 3 LDS : 32 FFMA per k-step. Float4 LDG/STG.
// ---------------------------------------------------------------------------
__device__ __forceinline__ void conv1x1_body(
    const float* __restrict__ in, const float* __restrict__ w,
    const float* __restrict__ bias, const float* __restrict__ resid,
    float* __restrict__ out)
{
    extern __shared__ float sm[];
    float* xs = sm;             // [64][128] activation tile
    float* ws = sm + 64*128;    // [64][64]  weights TRANSPOSED: ws[c*64+f]
    float* bs = ws + 64*64;     // [64]

    int tid = threadIdx.x;

    // transpose weights into smem (one-time, 16KB)
    for (int i = tid; i < 64*64; i += 256) {
        int c = i >> 6, f = i & 63;
        ws[i] = w[f*64 + c];
    }
    if (tid < 64) bs[tid] = bias[tid];

    int pix0 = blockIdx.x * 128;     // 16384 % 128 == 0 -> tile within one batch
    int b    = pix0 >> 14;
    int p    = pix0 & (HW - 1);
    const float* inp = in + (size_t)b*CHW + p;   // 512B aligned

    // activation tile: 2048 float4, 8 per thread, coalesced
    const float4* inp4 = (const float4*)inp;
    float4* xs4 = (float4*)xs;
    #pragma unroll
    for (int i = tid; i < 2048; i += 256) {
        int c = i >> 5, q = i & 31;
        xs4[i] = inp4[c*(HW/4) + q];
    }
    __syncthreads();

    int fg   = tid >> 5;     // features fg*8 .. fg*8+7 (uniform per warp)
    int lane = tid & 31;     // pixels lane*4 .. lane*4+3

    float acc[8][4];
    #pragma unroll
    for (int j = 0; j < 8; j++)
        #pragma unroll
        for (int k = 0; k < 4; k++) acc[j][k] = 0.f;

    const float* wp = ws + fg*8;
    const float* xp = xs + lane*4;

    #pragma unroll 4
    for (int c = 0; c < 64; c++) {
        float4 w0 = *(const float4*)(wp + c*64);      // broadcast
        float4 w1 = *(const float4*)(wp + c*64 + 4);  // broadcast
        float4 xv = *(const float4*)(xp + c*128);     // conflict-free 4-phase
        float wr[8] = {w0.x, w0.y, w0.z, w0.w, w1.x, w1.y, w1.z, w1.w};
        float xr[4] = {xv.x, xv.y, xv.z, xv.w};
        #pragma unroll
        for (int j = 0; j < 8; j++)
            #pragma unroll
            for (int k = 0; k < 4; k++)
                acc[j][k] += wr[j]*xr[k];
    }

    float* outp = out + (size_t)b*CHW + p + lane*4;
    const float* rp = resid ? (resid + (size_t)b*CHW + p + lane*4) : nullptr;
    #pragma unroll
    for (int j = 0; j < 8; j++) {
        int f = fg*8 + j;
        float bv = bs[f];
        float4 r;
        r.x = acc[j][0] + bv; r.y = acc[j][1] + bv;
        r.z = acc[j][2] + bv; r.w = acc[j][3] + bv;
        if (rp) {
            float4 rv = *(const float4*)(rp + (size_t)f*HW);
            r.x += rv.x; r.y += rv.y; r.z += rv.z; r.w += rv.w;
        }
        *(float4*)(outp + (size_t)f*HW) = r;
    }
}

// Fused Q-proj and V-proj: blockIdx.y selects which conv this block does.
__global__ void __launch_bounds__(256, 3) qv_conv_kernel(
    const float* __restrict__ x,  const float* __restrict__ y,
    const float* __restrict__ wx, const float* __restrict__ bx,
    const float* __restrict__ wy, const float* __restrict__ by,
    float* __restrict__ Q, float* __restrict__ V)
{
    if (blockIdx.y == 0) conv1x1_body(y, wy, by, nullptr, Q);
    else                 conv1x1_body(x, wx, bx, nullptr, V);
}

__global__ void __launch_bounds__(256, 3) out_conv_kernel(
    const float* __restrict__ in, const float* __restrict__ w,
    const float* __restrict__ bias, const float* __restrict__ resid,
    float* __restrict__ out)
{
    conv1x1_body(in, w, bias, resid, out);
}

// ---------------------------------------------------------------------------
// Local attention (5x5 window, zero-padded).
// Tile: interior 16h x 32w, halo 20 x 36 = 720 positions.
// smem: one [64][720] buffer (184.3KB), reused for Q then V.
// Halo-load index math (divisions) hoisted out of the channel loop.
// Compute c-loops unrolled x2 to overlap LDS latency with FFMA.
// ---------------------------------------------------------------------------
#define HT 16
#define WT 32
#define HR (HT + 4)     // 20
#define WC (WT + 4)     // 36
#define NPOS (HR * WC)  // 720

__global__ void __launch_bounds__(256, 1) attn_kernel(
    const float* __restrict__ Q, const float* __restrict__ V,
    float* __restrict__ O)
{
    extern __shared__ float s[];   // [64][NPOS]

    int tid = threadIdx.x;
    int wx  = tid & 31;            // column within tile
    int hy  = tid >> 5;            // row pair: rows hy*2, hy*2+1
    int b   = blockIdx.z;
    int h0  = blockIdx.y * HT;
    int w0  = blockIdx.x * WT;

    // ---- precompute halo load slots (index math ONCE, reused both phases) --
    int  spos[3];
    int  goff[3];
    int  gval[3];
    #pragma unroll
    for (int q = 0; q < 3; q++) {
        int pos = tid + q*256;
        if (pos >= NPOS) pos = NPOS - 1;        // harmless duplicate slot
        int r   = pos / WC;
        int col = pos - r*WC;
        int gh  = h0 + r - 2;
        int gw  = w0 + col - 2;
        spos[q] = pos;
        gval[q] = ((unsigned)gh < 128u && (unsigned)gw < 128u) ? 1 : 0;
        goff[q] = gh*128 + gw;
    }
    int nslot = (tid + 512 < NPOS) ? 3 : 2;     // NPOS=720 -> tid<208 gets 3

    // ---- load Q halo tile ----
    const float* Qb = Q + (size_t)b*CHW;
    #pragma unroll 2
    for (int c = 0; c < 64; c++) {
        const float* src = Qb + c*HW;
        float* dst = s + c*NPOS;
        #pragma unroll
        for (int q = 0; q < 3; q++) {
            if (q < nslot)
                dst[spos[q]] = gval[q] ? src[goff[q]] : 0.f;
        }
    }
    __syncthreads();

    int r0 = hy*2;
    float A1[25], A2[25];
    #pragma unroll
    for (int k = 0; k < 25; k++) { A1[k] = 0.f; A2[k] = 0.f; }

    #pragma unroll 2
    for (int c = 0; c < 64; c++) {
        const float* qs = s + c*NPOS + r0*WC + wx;
        float n[6][5];
        #pragma unroll
        for (int j = 0; j < 6; j++)
            #pragma unroll
            for (int i = 0; i < 5; i++)
                n[j][i] = qs[j*WC + i];
        float q1 = n[2][2];
        float q2 = n[3][2];
        #pragma unroll
        for (int j = 0; j < 5; j++)
            #pragma unroll
            for (int i = 0; i < 5; i++) {
                A1[j*5+i] += q1 * n[j][i];
                A2[j*5+i] += q2 * n[j+1][i];
            }
    }

    // ---- softmax over 25 neighbors ----
    {
        float m1 = A1[0], m2 = A2[0];
        #pragma unroll
        for (int k = 1; k < 25; k++) { m1 = fmaxf(m1, A1[k]); m2 = fmaxf(m2, A2[k]); }
        float s1 = 0.f, s2 = 0.f;
        #pragma unroll
        for (int k = 0; k < 25; k++) {
            A1[k] = __expf(A1[k] - m1); s1 += A1[k];
            A2[k] = __expf(A2[k] - m2); s2 += A2[k];
        }
        float i1 = 1.f/s1, i2 = 1.f/s2;
        #pragma unroll
        for (int k = 0; k < 25; k++) { A1[k] *= i1; A2[k] *= i2; }
    }

    __syncthreads();   // everyone done reading Q tile

    // ---- load V halo tile into the same buffer (reuse precomputed slots) ---
    const float* Vb = V + (size_t)b*CHW;
    #pragma unroll 2
    for (int c = 0; c < 64; c++) {
        const float* src = Vb + c*HW;
        float* dst = s + c*NPOS;
        #pragma unroll
        for (int q = 0; q < 3; q++) {
            if (q < nslot)
                dst[spos[q]] = gval[q] ? src[goff[q]] : 0.f;
        }
    }
    __syncthreads();

    // ---- aggregate ----
    float* Ob = O + (size_t)b*CHW + (h0 + r0)*128 + (w0 + wx);
    #pragma unroll 2
    for (int c = 0; c < 64; c++) {
        const float* vs = s + c*NPOS + r0*WC + wx;
        float n[6][5];
        #pragma unroll
        for (int j = 0; j < 6; j++)
            #pragma unroll
            for (int i = 0; i < 5; i++)
                n[j][i] = vs[j*WC + i];
        float o1 = 0.f, o2 = 0.f;
        #pragma unroll
        for (int j = 0; j < 5; j++)
            #pragma unroll
            for (int i = 0; i < 5; i++) {
                o1 += A1[j*5+i] * n[j][i];
                o2 += A2[j*5+i] * n[j+1][i];
            }
        Ob[c*HW]       = o1;
        Ob[c*HW + 128] = o2;
    }
}

// ---------------------------------------------------------------------------
extern "C" void kernel_launch(void* const* d_in, const int* in_sizes, int n_in,
                              void* d_out, int out_size)
{
    const float* x  = (const float*)d_in[0];
    const float* y  = (const float*)d_in[1];
    const float* wx = (const float*)d_in[2];
    const float* bx = (const float*)d_in[3];
    const float* wy = (const float*)d_in[4];
    const float* by = (const float*)d_in[5];
    const float* wo = (const float*)d_in[6];
    const float* bo = (const float*)d_in[7];
    float* out = (float*)d_out;

    void *pQ, *pV, *pO;
    cudaGetSymbolAddress(&pQ, g_Q);
    cudaGetSymbolAddress(&pV, g_V);
    cudaGetSymbolAddress(&pO, g_O);

    const int conv_smem = (64*128 + 64*64 + 64) * 4;   // 49408 B
    const int attn_smem = 64*NPOS*4;                   // 184320 B
    cudaFuncSetAttribute(qv_conv_kernel,  cudaFuncAttributeMaxDynamicSharedMemorySize, conv_smem);
    cudaFuncSetAttribute(out_conv_kernel, cudaFuncAttributeMaxDynamicSharedMemorySize, conv_smem);
    cudaFuncSetAttribute(attn_kernel,     cudaFuncAttributeMaxDynamicSharedMemorySize, attn_smem);

    // q = wy @ y + by ; v = wx @ x + bx  (one fused launch, gridDim.y selects)
    qv_conv_kernel<<<dim3(NPIX/128, 2), 256, conv_smem>>>(
        x, y, wx, bx, wy, by, (float*)pQ, (float*)pV);

    // scores + softmax + aggregate
    attn_kernel<<<dim3(128/WT, 128/HT, 4), 256, attn_smem>>>(
        (const float*)pQ, (const float*)pV, (float*)pO);

    // out = wo @ O + bo + x
    out_conv_kernel<<<NPIX/128, 256, conv_smem>>>((const float*)pO, wo, bo, x, out);
}

// round 5
// speedup vs baseline: 1.3091x; 1.3091x over previous
#include <cuda_runtime.h>

#define HW   (128*128)        // 16384 pixels per (b,c) plane
#define CHW  (64*HW)          // one batch image, 64 channels
#define NPIX (4*HW)           // total pixels across batch

// Scratch tensors (allocation-free rule: __device__ globals)
__device__ float g_Q[4*CHW];
__device__ float g_V[4*CHW];
__device__ float g_O[4*CHW];

// ---------------------------------------------------------------------------
// conv1x1 body: out[b,f,p] = sum_c w[f,c]*in[b,c,p] + bias[f] (+ resid)
// Tile: 64 features x 256 pixels, 256 threads, 8f x 8px per thread.
// Weights transposed [c][f] in smem -> 2 broadcast LDS.128 per k-step;
// activations: 2 strided LDS.128 per k-step (software-pipelined one k ahead).
// ~10 crossbar cyc : 32 FFMA-issue cyc per warp per k-step -> FFMA-bound.
// ---------------------------------------------------------------------------
__device__ __forceinline__ void conv1x1_body(
    const float* __restrict__ in, const float* __restrict__ w,
    const float* __restrict__ bias, const float* __restrict__ resid,
    float* __restrict__ out)
{
    extern __shared__ float sm[];
    float* xs = sm;             // [64][256] activation tile (64KB)
    float* ws = sm + 64*256;    // [64][64]  weights TRANSPOSED: ws[c*64+f]
    float* bs = ws + 64*64;     // [64]

    int tid = threadIdx.x;

    // transpose weights into smem
    for (int i = tid; i < 64*64; i += 256) {
        int c = i >> 6, f = i & 63;
        ws[i] = w[f*64 + c];
    }
    if (tid < 64) bs[tid] = bias[tid];

    int pix0 = blockIdx.x * 256;     // 16384 % 256 == 0 -> tile within one batch
    int b    = pix0 >> 14;
    int p    = pix0 & (HW - 1);
    const float* inp = in + (size_t)b*CHW + p;

    // activation tile: 4096 float4, 16 per thread, coalesced
    const float4* inp4 = (const float4*)inp;
    float4* xs4 = (float4*)xs;
    #pragma unroll
    for (int i = tid; i < 4096; i += 256) {
        int c = i >> 6, q = i & 63;
        xs4[i] = inp4[c*(HW/4) + q];
    }
    __syncthreads();

    int fg   = tid >> 5;     // features fg*8 .. fg*8+7 (uniform per warp)
    int lane = tid & 31;     // pixels lane*4..+3 and lane*4+128..+131

    float acc[8][8];
    #pragma unroll
    for (int j = 0; j < 8; j++)
        #pragma unroll
        for (int k = 0; k < 8; k++) acc[j][k] = 0.f;

    const float* wp = ws + fg*8;
    const float* xp = xs + lane*4;

    // software pipeline: activation loads one k-step ahead
    float4 x0 = *(const float4*)(xp);
    float4 x1 = *(const float4*)(xp + 128);

    #pragma unroll 4
    for (int c = 0; c < 64; c++) {
        float4 x0n, x1n;
        if (c < 63) {
            x0n = *(const float4*)(xp + (c+1)*256);
            x1n = *(const float4*)(xp + (c+1)*256 + 128);
        }
        float4 w0 = *(const float4*)(wp + c*64);      // broadcast
        float4 w1 = *(const float4*)(wp + c*64 + 4);  // broadcast

        float wr[8] = {w0.x, w0.y, w0.z, w0.w, w1.x, w1.y, w1.z, w1.w};
        float xr[8] = {x0.x, x0.y, x0.z, x0.w, x1.x, x1.y, x1.z, x1.w};
        #pragma unroll
        for (int j = 0; j < 8; j++)
            #pragma unroll
            for (int k = 0; k < 8; k++)
                acc[j][k] += wr[j]*xr[k];

        x0 = x0n; x1 = x1n;
    }

    float* outp = out + (size_t)b*CHW + p + lane*4;
    const float* rp = resid ? (resid + (size_t)b*CHW + p + lane*4) : nullptr;
    #pragma unroll
    for (int j = 0; j < 8; j++) {
        int f = fg*8 + j;
        float bv = bs[f];
        #pragma unroll
        for (int h = 0; h < 2; h++) {
            float4 r;
            r.x = acc[j][h*4+0] + bv; r.y = acc[j][h*4+1] + bv;
            r.z = acc[j][h*4+2] + bv; r.w = acc[j][h*4+3] + bv;
            if (rp) {
                float4 rv = *(const float4*)(rp + (size_t)f*HW + h*128);
                r.x += rv.x; r.y += rv.y; r.z += rv.z; r.w += rv.w;
            }
            *(float4*)(outp + (size_t)f*HW + h*128) = r;
        }
    }
}

// Fused Q-proj and V-proj: blockIdx.y selects which conv this block does.
__global__ void __launch_bounds__(256, 2) qv_conv_kernel(
    const float* __restrict__ x,  const float* __restrict__ y,
    const float* __restrict__ wx, const float* __restrict__ bx,
    const float* __restrict__ wy, const float* __restrict__ by,
    float* __restrict__ Q, float* __restrict__ V)
{
    if (blockIdx.y == 0) conv1x1_body(y, wy, by, nullptr, Q);
    else                 conv1x1_body(x, wx, bx, nullptr, V);
}

__global__ void __launch_bounds__(256, 2) out_conv_kernel(
    const float* __restrict__ in, const float* __restrict__ w,
    const float* __restrict__ bias, const float* __restrict__ resid,
    float* __restrict__ out)
{
    conv1x1_body(in, w, bias, resid, out);
}

// ---------------------------------------------------------------------------
// Local attention (5x5 window, zero-padded) — exact R2 version (measured-good).
// Tile: interior 16h x 32w, halo 20 x 36 = 720 positions.
// smem: one [64][720] buffer (184.3KB), reused for Q then V.
// Thread: 2 vertically-adjacent pixels -> 6x5 shared window per channel.
// ---------------------------------------------------------------------------
#define HT 16
#define WT 32
#define HR (HT + 4)     // 20
#define WC (WT + 4)     // 36
#define NPOS (HR * WC)  // 720

__global__ void __launch_bounds__(256, 1) attn_kernel(
    const float* __restrict__ Q, const float* __restrict__ V,
    float* __restrict__ O)
{
    extern __shared__ float s[];   // [64][NPOS]

    int tid = threadIdx.x;
    int wx  = tid & 31;            // column within tile
    int hy  = tid >> 5;            // row pair: rows hy*2, hy*2+1
    int b   = blockIdx.z;
    int h0  = blockIdx.y * HT;
    int w0  = blockIdx.x * WT;

    // ---- load Q halo tile (zero padding at image borders) ----
    const float* Qb = Q + (size_t)b*CHW;
    for (int i = tid; i < 64*NPOS; i += 256) {
        int c   = i / NPOS;
        int pos = i - c*NPOS;
        int r   = pos / WC;
        int col = pos - r*WC;
        int gh  = h0 + r - 2;
        int gw  = w0 + col - 2;
        float v = 0.f;
        if ((unsigned)gh < 128u && (unsigned)gw < 128u)
            v = Qb[c*HW + gh*128 + gw];
        s[i] = v;
    }
    __syncthreads();

    int r0 = hy*2;
    float A1[25], A2[25];
    #pragma unroll
    for (int k = 0; k < 25; k++) { A1[k] = 0.f; A2[k] = 0.f; }

    for (int c = 0; c < 64; c++) {
        const float* qs = s + c*NPOS + r0*WC + wx;
        float n[6][5];
        #pragma unroll
        for (int j = 0; j < 6; j++)
            #pragma unroll
            for (int i = 0; i < 5; i++)
                n[j][i] = qs[j*WC + i];
        float q1 = n[2][2];   // center of pixel (h0+r0,   w0+wx)
        float q2 = n[3][2];   // center of pixel (h0+r0+1, w0+wx)
        #pragma unroll
        for (int j = 0; j < 5; j++)
            #pragma unroll
            for (int i = 0; i < 5; i++) {
                A1[j*5+i] += q1 * n[j][i];
                A2[j*5+i] += q2 * n[j+1][i];
            }
    }

    // ---- softmax over 25 neighbors ----
    {
        float m1 = A1[0], m2 = A2[0];
        #pragma unroll
        for (int k = 1; k < 25; k++) { m1 = fmaxf(m1, A1[k]); m2 = fmaxf(m2, A2[k]); }
        float s1 = 0.f, s2 = 0.f;
        #pragma unroll
        for (int k = 0; k < 25; k++) {
            A1[k] = __expf(A1[k] - m1); s1 += A1[k];
            A2[k] = __expf(A2[k] - m2); s2 += A2[k];
        }
        float i1 = 1.f/s1, i2 = 1.f/s2;
        #pragma unroll
        for (int k = 0; k < 25; k++) { A1[k] *= i1; A2[k] *= i2; }
    }

    __syncthreads();   // everyone done reading Q tile

    // ---- load V halo tile into the same buffer ----
    const float* Vb = V + (size_t)b*CHW;
    for (int i = tid; i < 64*NPOS; i += 256) {
        int c   = i / NPOS;
        int pos = i - c*NPOS;
        int r   = pos / WC;
        int col = pos - r*WC;
        int gh  = h0 + r - 2;
        int gw  = w0 + col - 2;
        float v = 0.f;
        if ((unsigned)gh < 128u && (unsigned)gw < 128u)
            v = Vb[c*HW + gh*128 + gw];
        s[i] = v;
    }
    __syncthreads();

    // ---- aggregate ----
    float* Ob = O + (size_t)b*CHW + (h0 + r0)*128 + (w0 + wx);
    for (int c = 0; c < 64; c++) {
        const float* vs = s + c*NPOS + r0*WC + wx;
        float n[6][5];
        #pragma unroll
        for (int j = 0; j < 6; j++)
            #pragma unroll
            for (int i = 0; i < 5; i++)
                n[j][i] = vs[j*WC + i];
        float o1 = 0.f, o2 = 0.f;
        #pragma unroll
        for (int j = 0; j < 5; j++)
            #pragma unroll
            for (int i = 0; i < 5; i++) {
                o1 += A1[j*5+i] * n[j][i];
                o2 += A2[j*5+i] * n[j+1][i];
            }
        Ob[c*HW]       = o1;
        Ob[c*HW + 128] = o2;
    }
}

// ---------------------------------------------------------------------------
extern "C" void kernel_launch(void* const* d_in, const int* in_sizes, int n_in,
                              void* d_out, int out_size)
{
    const float* x  = (const float*)d_in[0];
    const float* y  = (const float*)d_in[1];
    const float* wx = (const float*)d_in[2];
    const float* bx = (const float*)d_in[3];
    const float* wy = (const float*)d_in[4];
    const float* by = (const float*)d_in[5];
    const float* wo = (const float*)d_in[6];
    const float* bo = (const float*)d_in[7];
    float* out = (float*)d_out;

    void *pQ, *pV, *pO;
    cudaGetSymbolAddress(&pQ, g_Q);
    cudaGetSymbolAddress(&pV, g_V);
    cudaGetSymbolAddress(&pO, g_O);

    const int conv_smem = (64*256 + 64*64 + 64) * 4;   // 82176 B
    const int attn_smem = 64*NPOS*4;                   // 184320 B
    cudaFuncSetAttribute(qv_conv_kernel,  cudaFuncAttributeMaxDynamicSharedMemorySize, conv_smem);
    cudaFuncSetAttribute(out_conv_kernel, cudaFuncAttributeMaxDynamicSharedMemorySize, conv_smem);
    cudaFuncSetAttribute(attn_kernel,     cudaFuncAttributeMaxDynamicSharedMemorySize, attn_smem);

    // q = wy @ y + by ; v = wx @ x + bx  (one fused launch, gridDim.y selects)
    qv_conv_kernel<<<dim3(NPIX/256, 2), 256, conv_smem>>>(
        x, y, wx, bx, wy, by, (float*)pQ, (float*)pV);

    // scores + softmax + aggregate
    attn_kernel<<<dim3(128/WT, 128/HT, 4), 256, attn_smem>>>(
        (const float*)pQ, (const float*)pV, (float*)pO);

    // out = wo @ O + bo + x
    out_conv_kernel<<<NPIX/256, 256, conv_smem>>>((const float*)pO, wo, bo, x, out);
}

// round 8
// speedup vs baseline: 1.4316x; 1.0936x over previous
#include <cuda_runtime.h>

#define HW   (128*128)        // 16384 pixels per (b,c) plane
#define CHW  (64*HW)          // one batch image, 64 channels
#define NPIX (4*HW)           // total pixels across batch

// Scratch tensors (allocation-free rule: __device__ globals)
__device__ float g_Q[4*CHW];
__device__ float g_V[4*CHW];
__device__ float g_O[4*CHW];

// ---------------------------------------------------------------------------
// conv1x1 body (R5, measured-good): out[b,f,p] = sum_c w[f,c]*in[b,c,p]
//   + bias[f] (+ resid).  Tile 64f x 256px, 256 threads, 8f x 8px per thread.
// Weights transposed [c][f] in smem -> 2 broadcast LDS.128 per k-step;
// activations 2 strided LDS.128 per k-step, software-pipelined one k ahead.
// ---------------------------------------------------------------------------
__device__ __forceinline__ void conv1x1_body(
    const float* __restrict__ in, const float* __restrict__ w,
    const float* __restrict__ bias, const float* __restrict__ resid,
    float* __restrict__ out)
{
    extern __shared__ float sm[];
    float* xs = sm;             // [64][256] activation tile (64KB)
    float* ws = sm + 64*256;    // [64][64]  weights TRANSPOSED: ws[c*64+f]
    float* bs = ws + 64*64;     // [64]

    int tid = threadIdx.x;

    for (int i = tid; i < 64*64; i += 256) {
        int c = i >> 6, f = i & 63;
        ws[i] = w[f*64 + c];
    }
    if (tid < 64) bs[tid] = bias[tid];

    int pix0 = blockIdx.x * 256;
    int b    = pix0 >> 14;
    int p    = pix0 & (HW - 1);
    const float* inp = in + (size_t)b*CHW + p;

    const float4* inp4 = (const float4*)inp;
    float4* xs4 = (float4*)xs;
    #pragma unroll
    for (int i = tid; i < 4096; i += 256) {
        int c = i >> 6, q = i & 63;
        xs4[i] = inp4[c*(HW/4) + q];
    }
    __syncthreads();

    int fg   = tid >> 5;
    int lane = tid & 31;

    float acc[8][8];
    #pragma unroll
    for (int j = 0; j < 8; j++)
        #pragma unroll
        for (int k = 0; k < 8; k++) acc[j][k] = 0.f;

    const float* wp = ws + fg*8;
    const float* xp = xs + lane*4;

    float4 x0 = *(const float4*)(xp);
    float4 x1 = *(const float4*)(xp + 128);

    #pragma unroll 4
    for (int c = 0; c < 64; c++) {
        float4 x0n, x1n;
        if (c < 63) {
            x0n = *(const float4*)(xp + (c+1)*256);
            x1n = *(const float4*)(xp + (c+1)*256 + 128);
        }
        float4 w0 = *(const float4*)(wp + c*64);
        float4 w1 = *(const float4*)(wp + c*64 + 4);

        float wr[8] = {w0.x, w0.y, w0.z, w0.w, w1.x, w1.y, w1.z, w1.w};
        float xr[8] = {x0.x, x0.y, x0.z, x0.w, x1.x, x1.y, x1.z, x1.w};
        #pragma unroll
        for (int j = 0; j < 8; j++)
            #pragma unroll
            for (int k = 0; k < 8; k++)
                acc[j][k] += wr[j]*xr[k];

        x0 = x0n; x1 = x1n;
    }

    float* outp = out + (size_t)b*CHW + p + lane*4;
    const float* rp = resid ? (resid + (size_t)b*CHW + p + lane*4) : nullptr;
    #pragma unroll
    for (int j = 0; j < 8; j++) {
        int f = fg*8 + j;
        float bv = bs[f];
        #pragma unroll
        for (int h = 0; h < 2; h++) {
            float4 r;
            r.x = acc[j][h*4+0] + bv; r.y = acc[j][h*4+1] + bv;
            r.z = acc[j][h*4+2] + bv; r.w = acc[j][h*4+3] + bv;
            if (rp) {
                float4 rv = *(const float4*)(rp + (size_t)f*HW + h*128);
                r.x += rv.x; r.y += rv.y; r.z += rv.z; r.w += rv.w;
            }
            *(float4*)(outp + (size_t)f*HW + h*128) = r;
        }
    }
}

__global__ void __launch_bounds__(256, 2) qv_conv_kernel(
    const float* __restrict__ x,  const float* __restrict__ y,
    const float* __restrict__ wx, const float* __restrict__ bx,
    const float* __restrict__ wy, const float* __restrict__ by,
    float* __restrict__ Q, float* __restrict__ V)
{
    if (blockIdx.y == 0) conv1x1_body(y, wy, by, nullptr, Q);
    else                 conv1x1_body(x, wx, bx, nullptr, V);
}

__global__ void __launch_bounds__(256, 2) out_conv_kernel(
    const float* __restrict__ in, const float* __restrict__ w,
    const float* __restrict__ bias, const float* __restrict__ resid,
    float* __restrict__ out)
{
    conv1x1_body(in, w, bias, resid, out);
}

// ---------------------------------------------------------------------------
// Local attention (5x5 window, zero-padded) — high-occupancy variant.
// Tile: interior 16h x 32w (512 px), halo 20 x 36 = 720 positions.
// 512 threads, ONE pixel per thread -> 16 warps/CTA for latency hiding.
// Channels processed in two 32-ch chunks so smem = 32*720*4 = 92KB.
// Score accumulators A[25] live in regs across chunks.
// ---------------------------------------------------------------------------
#define HT 16
#define WT 32
#define HR (HT + 4)     // 20
#define WC (WT + 4)     // 36
#define NPOS (HR * WC)  // 720
#define CCH 32          // channels per chunk
#define ATTN_SMEM (CCH*NPOS*4)   // 92160 B

__device__ __forceinline__ void load_halo_chunk(
    const float* __restrict__ src,      // base of this chunk: X + b*CHW + ck*CCH*HW
    float* __restrict__ s, int tid, int h0, int w0)
{
    #pragma unroll 5
    for (int i = tid; i < CCH*NPOS; i += 512) {
        int c   = i / NPOS;
        int pos = i - c*NPOS;
        int r   = pos / WC;
        int col = pos - r*WC;
        int gh  = h0 + r - 2;
        int gw  = w0 + col - 2;
        float v = 0.f;
        if ((unsigned)gh < 128u && (unsigned)gw < 128u)
            v = src[c*HW + gh*128 + gw];
        s[i] = v;
    }
}

__global__ void __launch_bounds__(512, 1) attn_kernel(
    const float* __restrict__ Q, const float* __restrict__ V,
    float* __restrict__ O)
{
    extern __shared__ float s[];   // [CCH][NPOS]

    int tid = threadIdx.x;
    int wx  = tid & 31;            // pixel column within tile
    int hy  = tid >> 5;            // pixel row within tile (0..15)
    int b   = blockIdx.z;
    int h0  = blockIdx.y * HT;
    int w0  = blockIdx.x * WT;

    float A[25];
    #pragma unroll
    for (int k = 0; k < 25; k++) A[k] = 0.f;

    // ---- scores: two 32-channel chunks ----
    const float* Qb = Q + (size_t)b*CHW;
    #pragma unroll
    for (int ck = 0; ck < 2; ck++) {
        load_halo_chunk(Qb + ck*CCH*HW, s, tid, h0, w0);
        __syncthreads();

        const float* base0 = s + hy*WC + wx;
        for (int c = 0; c < CCH; c++) {
            const float* qs = base0 + c*NPOS;
            float n[25];
            #pragma unroll
            for (int j = 0; j < 5; j++)
                #pragma unroll
                for (int i = 0; i < 5; i++)
                    n[j*5+i] = qs[j*WC + i];
            float q = n[12];                 // center
            #pragma unroll
            for (int k = 0; k < 25; k++)
                A[k] += q * n[k];
        }
        __syncthreads();
    }

    // ---- softmax over 25 neighbors ----
    {
        float m = A[0];
        #pragma unroll
        for (int k = 1; k < 25; k++) m = fmaxf(m, A[k]);
        float sum = 0.f;
        #pragma unroll
        for (int k = 0; k < 25; k++) { A[k] = __expf(A[k] - m); sum += A[k]; }
        float inv = 1.f/sum;
        #pragma unroll
        for (int k = 0; k < 25; k++) A[k] *= inv;
    }

    // ---- aggregate: two 32-channel chunks, write per-channel output ----
    const float* Vb = V + (size_t)b*CHW;
    float* Ob = O + (size_t)b*CHW + (h0 + hy)*128 + (w0 + wx);
    #pragma unroll
    for (int ck = 0; ck < 2; ck++) {
        load_halo_chunk(Vb + ck*CCH*HW, s, tid, h0, w0);
        __syncthreads();

        const float* base0 = s + hy*WC + wx;
        for (int c = 0; c < CCH; c++) {
            const float* vs = base0 + c*NPOS;
            float o = 0.f;
            #pragma unroll
            for (int j = 0; j < 5; j++)
                #pragma unroll
                for (int i = 0; i < 5; i++)
                    o += A[j*5+i] * vs[j*WC + i];
            Ob[(size_t)(ck*CCH + c)*HW] = o;   // coalesced over wx
        }
        __syncthreads();
    }
}

// ---------------------------------------------------------------------------
extern "C" void kernel_launch(void* const* d_in, const int* in_sizes, int n_in,
                              void* d_out, int out_size)
{
    const float* x  = (const float*)d_in[0];
    const float* y  = (const float*)d_in[1];
    const float* wx = (const float*)d_in[2];
    const float* bx = (const float*)d_in[3];
    const float* wy = (const float*)d_in[4];
    const float* by = (const float*)d_in[5];
    const float* wo = (const float*)d_in[6];
    const float* bo = (const float*)d_in[7];
    float* out = (float*)d_out;

    void *pQ, *pV, *pO;
    cudaGetSymbolAddress(&pQ, g_Q);
    cudaGetSymbolAddress(&pV, g_V);
    cudaGetSymbolAddress(&pO, g_O);

    const int conv_smem = (64*256 + 64*64 + 64) * 4;   // 82176 B
    cudaFuncSetAttribute(qv_conv_kernel,  cudaFuncAttributeMaxDynamicSharedMemorySize, conv_smem);
    cudaFuncSetAttribute(out_conv_kernel, cudaFuncAttributeMaxDynamicSharedMemorySize, conv_smem);
    cudaFuncSetAttribute(attn_kernel,     cudaFuncAttributeMaxDynamicSharedMemorySize, ATTN_SMEM);

    // q = wy @ y + by ; v = wx @ x + bx  (one fused launch, gridDim.y selects)
    qv_conv_kernel<<<dim3(NPIX/256, 2), 256, conv_smem>>>(
        x, y, wx, bx, wy, by, (float*)pQ, (float*)pV);

    // scores + softmax + aggregate
    attn_kernel<<<dim3(128/WT, 128/HT, 4), 512, ATTN_SMEM>>>(
        (const float*)pQ, (const float*)pV, (float*)pO);

    // out = wo @ O + bo + x
    out_conv_kernel<<<NPIX/256, 256, conv_smem>>>((const float*)pO, wo, bo, x, out);
}